// round 15
// baseline (speedup 1.0000x reference)
#include <cuda_runtime.h>

// IF spiking neuron, T=4. FINAL champion (R8 config; best & lowest-variance
// of 14 rounds: 43.49/43.49/43.55/44.64us across 4 runs of this exact code).
// x:[T*B,C,H,W] fp32; per position: mem=0.5*th; for t: mem+=x[t];
// s=(mem>=th)?th:0; out[t]=s; mem-=s. Bit-exact fp32 order vs reference.
//
// 128 MiB in + 128 MiB out; both streams exceed the 126MB L2 -> 268MB DRAM
// traffic is compulsory; wall = traffic / BW_eff at the chip's measured
// mixed read/write HBM3e plateau (~6.0-6.15 TB/s, ~77% of 8TB/s spec).
// Closed axes (all neutral or regressions): MLP(4/8), vector width(128/256b),
// block(256/512/1024), persistent vs saturating grid, full cache-policy
// matrix, STG vs TMA bulk stores, occupancy 38-85%. Compute <10%, issue 13%
// -> purely HBM-bound, saturated.
//
// Structure: one thread = one 32B lane across the 4 timestep slabs.
// 4 independent LDG.E.256 batched up-front (128B in flight per thread),
// in-register membrane recurrence (8 independent scalar chains), 4 STG.E.256.
// 512 threads/block, 2048 blocks (exact), 48 regs.

#define TSTEPS 4

struct __align__(32) f8 { float v[8]; };

__device__ __forceinline__ f8 ldg256(const f8* p) {
    f8 r;
    asm volatile("ld.global.v8.f32 {%0,%1,%2,%3,%4,%5,%6,%7}, [%8];"
                 : "=f"(r.v[0]), "=f"(r.v[1]), "=f"(r.v[2]), "=f"(r.v[3]),
                   "=f"(r.v[4]), "=f"(r.v[5]), "=f"(r.v[6]), "=f"(r.v[7])
                 : "l"(p));
    return r;
}

__device__ __forceinline__ void stg256(f8* p, const f8& r) {
    asm volatile("st.global.v8.f32 [%0], {%1,%2,%3,%4,%5,%6,%7,%8};"
                 :: "l"(p),
                    "f"(r.v[0]), "f"(r.v[1]), "f"(r.v[2]), "f"(r.v[3]),
                    "f"(r.v[4]), "f"(r.v[5]), "f"(r.v[6]), "f"(r.v[7])
                 : "memory");
}

__global__ __launch_bounds__(512)
void if_kernel(const f8* __restrict__ x,
               const float* __restrict__ thresh,
               f8* __restrict__ out,
               int stride8)
{
    int i = blockIdx.x * blockDim.x + threadIdx.x;

    const float th = __ldg(thresh);
    const float m0 = 0.5f * th;

    // 4 independent strided 32B loads (128B in flight per thread).
    f8 xt[TSTEPS];
#pragma unroll
    for (int t = 0; t < TSTEPS; t++)
        xt[t] = ldg256(&x[i + t * stride8]);

    // In-place membrane recurrence: 8 independent scalar chains.
#pragma unroll
    for (int c = 0; c < 8; c++) {
        float m = m0;
#pragma unroll
        for (int t = 0; t < TSTEPS; t++) {
            m += xt[t].v[c];
            float s = (m >= th) ? th : 0.0f;
            xt[t].v[c] = s;
            m -= s;
        }
    }

#pragma unroll
    for (int t = 0; t < TSTEPS; t++)
        stg256(&out[i + t * stride8], xt[t]);
}

extern "C" void kernel_launch(void* const* d_in, const int* in_sizes, int n_in,
                              void* d_out, int out_size)
{
    const float* x      = (const float*)d_in[0];
    const float* thresh = (const float*)d_in[1];
    float* out          = (float*)d_out;

    int n = in_sizes[0];              // total elements = 2^27
    int stride = n / TSTEPS;          // elements per timestep slab = 8388608
    int stride8 = stride / 8;         // f8 units per slab = 1048576

    int threads = 512;
    int blocks = stride8 / threads;   // 2048, exact
    if_kernel<<<blocks, threads>>>(
        (const f8*)x, thresh, (f8*)out, stride8);
}

// round 16
// speedup vs baseline: 1.0324x; 1.0324x over previous
#include <cuda_runtime.h>

// IF spiking neuron, T=4. FINAL champion (R8 config).
// Best measured: 43.488us (x2); env band 43.5-45.0us across holds while
// in-kernel ncu dur stays 35.2-36.1us -> wall drift is DVFS/hold state.
//
// x:[T*B,C,H,W] fp32; per position: mem=0.5*th; for t: mem+=x[t];
// s=(mem>=th)?th:0; out[t]=s; mem-=s. Bit-exact fp32 order vs reference.
//
// 128 MiB in + 128 MiB out; both streams exceed the 126MB L2 -> 268MB DRAM
// traffic is compulsory; wall = traffic / BW_eff at the chip's measured
// mixed read/write HBM3e plateau (~6.0-6.15 TB/s, ~77% of 8TB/s spec).
// Closed axes over 15 rounds (all neutral or regressions): MLP(4/8),
// vector width(128/256b), block(256/512/1024), persistent vs saturating
// grid, full cache-policy matrix, STG vs TMA bulk stores, occupancy 38-85%.
// Compute <10%, issue 13% in every profile -> purely HBM-bound, saturated.
//
// Structure: one thread = one 32B lane across the 4 timestep slabs.
// 4 independent LDG.E.256 batched up-front (128B in flight per thread),
// in-register membrane recurrence (8 independent scalar chains), 4 STG.E.256.
// 512 threads/block, 2048 blocks (exact), 48 regs.

#define TSTEPS 4

struct __align__(32) f8 { float v[8]; };

__device__ __forceinline__ f8 ldg256(const f8* p) {
    f8 r;
    asm volatile("ld.global.v8.f32 {%0,%1,%2,%3,%4,%5,%6,%7}, [%8];"
                 : "=f"(r.v[0]), "=f"(r.v[1]), "=f"(r.v[2]), "=f"(r.v[3]),
                   "=f"(r.v[4]), "=f"(r.v[5]), "=f"(r.v[6]), "=f"(r.v[7])
                 : "l"(p));
    return r;
}

__device__ __forceinline__ void stg256(f8* p, const f8& r) {
    asm volatile("st.global.v8.f32 [%0], {%1,%2,%3,%4,%5,%6,%7,%8};"
                 :: "l"(p),
                    "f"(r.v[0]), "f"(r.v[1]), "f"(r.v[2]), "f"(r.v[3]),
                    "f"(r.v[4]), "f"(r.v[5]), "f"(r.v[6]), "f"(r.v[7])
                 : "memory");
}

__global__ __launch_bounds__(512)
void if_kernel(const f8* __restrict__ x,
               const float* __restrict__ thresh,
               f8* __restrict__ out,
               int stride8)
{
    int i = blockIdx.x * blockDim.x + threadIdx.x;

    const float th = __ldg(thresh);
    const float m0 = 0.5f * th;

    // 4 independent strided 32B loads (128B in flight per thread).
    f8 xt[TSTEPS];
#pragma unroll
    for (int t = 0; t < TSTEPS; t++)
        xt[t] = ldg256(&x[i + t * stride8]);

    // In-place membrane recurrence: 8 independent scalar chains.
#pragma unroll
    for (int c = 0; c < 8; c++) {
        float m = m0;
#pragma unroll
        for (int t = 0; t < TSTEPS; t++) {
            m += xt[t].v[c];
            float s = (m >= th) ? th : 0.0f;
            xt[t].v[c] = s;
            m -= s;
        }
    }

#pragma unroll
    for (int t = 0; t < TSTEPS; t++)
        stg256(&out[i + t * stride8], xt[t]);
}

extern "C" void kernel_launch(void* const* d_in, const int* in_sizes, int n_in,
                              void* d_out, int out_size)
{
    const float* x      = (const float*)d_in[0];
    const float* thresh = (const float*)d_in[1];
    float* out          = (float*)d_out;

    int n = in_sizes[0];              // total elements = 2^27
    int stride = n / TSTEPS;          // elements per timestep slab = 8388608
    int stride8 = stride / 8;         // f8 units per slab = 1048576

    int threads = 512;
    int blocks = stride8 / threads;   // 2048, exact
    if_kernel<<<blocks, threads>>>(
        (const f8*)x, thresh, (f8*)out, stride8);
}